// round 15
// baseline (speedup 1.0000x reference)
#include <cuda_runtime.h>
#include <cuda_fp16.h>
#include <math.h>
#include <stdint.h>

#define BATCH   16
#define SEQ     17
#define NNODE   256
#define FDIM    64
#define LWIN    16
#define BP      256         // BATCH*LWIN
#define N1      512
#define OUTD    64
#define NTOT    (BP*N1)
#define SLOPE   0.01f

// ---------------- scratch ----------------------------------------------------
__device__ __half g_nfh [(size_t)BP*N1*FDIM];
__device__ __half g_adjh[(size_t)BP*N1*N1];     // 134 MB
__device__ __half g_th  [(size_t)BP*N1*FDIM];
__device__ __half g_oph [(size_t)BP*N1*OUTD];
__device__ float  g_part[2][BP][128];
__device__ float  g_coef[2][2][64];             // [1] used by k_final
__device__ __half g_Wh  [128*64];               // rows 0-63: th0*a ; 64-127: th1*a
__device__ float  g_cbuf[128];                  // [0..64): th0@d ; [64..128): th1@d

// ---------------- helpers ----------------------------------------------------
__device__ __forceinline__ uint32_t sptr(const void* p) {
    return (uint32_t)__cvta_generic_to_shared(p);
}
__device__ __forceinline__ void cp16(uint32_t d, const void* s) {
    asm volatile("cp.async.cg.shared.global [%0],[%1],16;" :: "r"(d), "l"(s));
}
#define CP_COMMIT asm volatile("cp.async.commit_group;")
#define CP_WAIT0  asm volatile("cp.async.wait_group 0;")
#define CP_WAIT1  asm volatile("cp.async.wait_group 1;")

__device__ __forceinline__ void mma_f16(float c[4], unsigned a0, unsigned a1,
                                        unsigned a2, unsigned a3,
                                        unsigned b0, unsigned b1) {
    asm volatile(
        "mma.sync.aligned.m16n8k16.row.col.f32.f16.f16.f32 "
        "{%0,%1,%2,%3},{%4,%5,%6,%7},{%8,%9},{%0,%1,%2,%3};"
        : "+f"(c[0]), "+f"(c[1]), "+f"(c[2]), "+f"(c[3])
        : "r"(a0), "r"(a1), "r"(a2), "r"(a3), "r"(b0), "r"(b1));
}
// A-fragment (16x16), row-major [m][k]
__device__ __forceinline__ void ldsm4h(unsigned& r0, unsigned& r1, unsigned& r2, unsigned& r3,
                                       const __half* base, int row0, int k0, int stride) {
    const int lane = threadIdx.x & 31;
    uint32_t a = sptr(base + (row0 + (lane & 15)) * stride + k0 + ((lane >> 4) << 3));
    asm volatile("ldmatrix.sync.aligned.m8n8.x4.shared.b16 {%0,%1,%2,%3},[%4];"
                 : "=r"(r0), "=r"(r1), "=r"(r2), "=r"(r3) : "r"(a));
}
// B-fragments from [n][k] storage: TWO adjacent n-tiles (n0, n0+8) in one x4
__device__ __forceinline__ void ldsm4h_n(unsigned& r0, unsigned& r1, unsigned& r2, unsigned& r3,
                                         const __half* base, int n0, int k0, int stride) {
    const int lane = threadIdx.x & 31;
    uint32_t a = sptr(base + (n0 + (lane & 7) + ((lane >> 4) << 3)) * stride
                      + k0 + (((lane >> 3) & 1) << 3));
    asm volatile("ldmatrix.sync.aligned.m8n8.x4.shared.b16 {%0,%1,%2,%3},[%4];"
                 : "=r"(r0), "=r"(r1), "=r"(r2), "=r"(r3) : "r"(a));
}
// B-fragments from [n][k] storage: ONE n-tile, TWO k-steps (k0, k0+16) in one x4
__device__ __forceinline__ void ldsm4h_nk(unsigned& r0, unsigned& r1, unsigned& r2, unsigned& r3,
                                          const __half* base, int n0, int k0, int stride) {
    const int lane = threadIdx.x & 31;
    uint32_t a = sptr(base + (n0 + (lane & 7)) * stride
                      + k0 + (((lane >> 3) & 1) << 3) + ((lane >> 4) << 4));
    asm volatile("ldmatrix.sync.aligned.m8n8.x4.shared.b16 {%0,%1,%2,%3},[%4];"
                 : "=r"(r0), "=r"(r1), "=r"(r2), "=r"(r3) : "r"(a));
}
// B-fragments from [k][n] storage: k-steps k0 and k0+16 of one n-tile (x4 trans)
__device__ __forceinline__ void ldsm4h_t(unsigned& r0, unsigned& r1, unsigned& r2, unsigned& r3,
                                         const __half* base, int k0, int n0, int stride) {
    const int lane = threadIdx.x & 31;
    uint32_t a = sptr(base + (k0 + lane) * stride + n0);
    asm volatile("ldmatrix.sync.aligned.m8n8.x4.trans.shared.b16 {%0,%1,%2,%3},[%4];"
                 : "=r"(r0), "=r"(r1), "=r"(r2), "=r"(r3) : "r"(a));
}
// Store a 16x16 accumulator tile (as half) via stmatrix x4. Same addr map as ldsm4h.
__device__ __forceinline__ void stsm4h(__half* base, int row0, int n0, int stride,
                                       unsigned p0, unsigned p1, unsigned p2, unsigned p3) {
    const int lane = threadIdx.x & 31;
    uint32_t a = sptr(base + (row0 + (lane & 15)) * stride + n0 + ((lane >> 4) << 3));
    asm volatile("stmatrix.sync.aligned.m8n8.x4.shared.b16 [%0], {%1,%2,%3,%4};"
                 :: "r"(a), "r"(p0), "r"(p1), "r"(p2), "r"(p3) : "memory");
}
__device__ __forceinline__ unsigned h2u(float a, float b) {
    __half2 h = __floats2half2_rn(a, b);
    return *reinterpret_cast<unsigned*>(&h);
}

// ---------------- K1: nf = gather(X) @ w2^T + b2 ----------------------------
__global__ void __launch_bounds__(256) k_nf(const float* __restrict__ x,
                                            const float* __restrict__ w2,
                                            const float* __restrict__ b2) {
    __shared__ __half xh[64 * 72];
    __shared__ __half wh[64 * 72];
    const int tile = blockIdx.x, batch = blockIdx.y, tid = threadIdx.x;
    const int b = batch / LWIN, l = batch % LWIN;

    for (int e = tid; e < 1024; e += 256) {
        const int row = e >> 4, c4 = e & 15;
        const int r = tile * 64 + row, m = r >> 8, n = r & 255;
        float4 xv = *(const float4*)(x + ((size_t)(b * SEQ + l + m) * NNODE + n) * FDIM + c4 * 4);
        *(__half2*)(xh + row * 72 + c4 * 4)     = __floats2half2_rn(xv.x, xv.y);
        *(__half2*)(xh + row * 72 + c4 * 4 + 2) = __floats2half2_rn(xv.z, xv.w);
        float4 wv = *(const float4*)(w2 + row * 64 + c4 * 4);
        *(__half2*)(wh + row * 72 + c4 * 4)     = __floats2half2_rn(wv.x, wv.y);
        *(__half2*)(wh + row * 72 + c4 * 4 + 2) = __floats2half2_rn(wv.z, wv.w);
    }
    __syncthreads();

    const int w = tid >> 5, lane = tid & 31;
    const int band = w >> 1, colg = w & 1;
    const int lq = lane >> 2, lr = lane & 3;
    float acc[4][4];
#pragma unroll
    for (int t = 0; t < 4; t++) { acc[t][0] = acc[t][1] = acc[t][2] = acc[t][3] = 0.f; }
#pragma unroll
    for (int ks = 0; ks < 4; ks++) {
        const int k0 = ks * 16;
        unsigned a0, a1, a2, a3; ldsm4h(a0, a1, a2, a3, xh, band * 16, k0, 72);
#pragma unroll
        for (int tt = 0; tt < 2; tt++) {
            unsigned b0, b1, b2v, b3v;
            ldsm4h_n(b0, b1, b2v, b3v, wh, colg * 32 + tt * 16, k0, 72);
            mma_f16(acc[tt * 2],     a0, a1, a2, a3, b0, b1);
            mma_f16(acc[tt * 2 + 1], a0, a1, a2, a3, b2v, b3v);
        }
    }
    const size_t ob = ((size_t)batch * N1 + tile * 64 + band * 16 + lq) * 64;
#pragma unroll
    for (int t = 0; t < 4; t++) {
        const int c = colg * 32 + t * 8 + lr * 2;
        const float bb0 = __ldg(b2 + c), bb1 = __ldg(b2 + c + 1);
        *(__half2*)(g_nfh + ob + c) = __floats2half2_rn(acc[t][0] + bb0, acc[t][1] + bb1);
        *(__half2*)(g_nfh + ob + (size_t)8 * 64 + c) = __floats2half2_rn(acc[t][2] + bb0, acc[t][3] + bb1);
    }
}

// ---------------- BN stats (streaming, half sources) --------------------------
__global__ void k_stats_p1(int which) {
    const int batch = blockIdx.x, tid = threadIdx.x;
    const int c = tid & 63, rg = tid >> 6;
    const __half* p = ((which == 0) ? g_nfh : g_oph) + (size_t)batch * N1 * 64;
    float s = 0.f, q = 0.f;
    for (int r = rg * 128; r < rg * 128 + 128; r++) {
        float v = __half2float(p[(size_t)r * 64 + c]);
        s += v; q += v * v;
    }
    __shared__ float sm[256], qm[256];
    sm[tid] = s; qm[tid] = q;
    __syncthreads();
    if (tid < 64) {
        g_part[which][batch][tid]      = sm[tid] + sm[tid + 64] + sm[tid + 128] + sm[tid + 192];
        g_part[which][batch][tid + 64] = qm[tid] + qm[tid + 64] + qm[tid + 128] + qm[tid + 192];
    }
}
__global__ void k_stats_p2(const float* __restrict__ w, const float* __restrict__ bb, int which) {
    const int c = threadIdx.x;
    float s = 0.f, q = 0.f;
    for (int b2 = 0; b2 < BP; b2++) { s += g_part[which][b2][c]; q += g_part[which][b2][c + 64]; }
    const float mu  = s / (float)NTOT;
    const float var = q / (float)NTOT - mu * mu;
    const float a   = w[c] * rsqrtf(var + 1e-5f);
    g_coef[which][0][c] = a;
    g_coef[which][1][c] = bb[c] - mu * a;
}

// ---------------- K1b: BN0 coefs + theta fold, fused (1 CTA, 128 thr) --------
__global__ void k_p2prep(const float* __restrict__ bn0w, const float* __restrict__ bn0b,
                         const float* __restrict__ th0w, const float* __restrict__ th1w) {
    __shared__ float ca[64], cd[64];
    const int tid = threadIdx.x;    // 128
    if (tid < 64) {
        float s = 0.f, q = 0.f;
        for (int b2 = 0; b2 < BP; b2++) { s += g_part[0][b2][tid]; q += g_part[0][b2][tid + 64]; }
        const float mu  = s / (float)NTOT;
        const float var = q / (float)NTOT - mu * mu;
        const float a   = bn0w[tid] * rsqrtf(var + 1e-5f);
        ca[tid] = a; cd[tid] = bn0b[tid] - mu * a;
    }
    __syncthreads();
    const int n = tid;
    const float* wr = (n < 64) ? (th0w + n * 64) : (th1w + (n - 64) * 64);
    float c = 0.f;
#pragma unroll 8
    for (int k = 0; k < 64; k++) {
        const float wv = wr[k];
        g_Wh[n * 64 + k] = __float2half(wv * ca[k]);
        c += wv * cd[k];
    }
    g_cbuf[n] = c;
}

// ---------------- K3: adj (softmax) + z1 fold + y=adj@nf + t = y@th1'^T ------
// smem bytes: nf_s[512*72]h @0 (reused: y_s head / Wh1 at +4608B)
//             adj_s[32*520]h @73728 (Wh0 aliases head)
//             reds @107008 | cbuf_s @108032 | rowsum_s @108544 | ypart @108672
__global__ void __launch_bounds__(512, 2) k_adj() {
    extern __shared__ char sraw[];
    __half* nf_s  = (__half*)sraw;
    __half* adj_s = (__half*)(sraw + 73728);
    __half* Wh0   = adj_s;                     // consumed before softmax writes
    float*  reds  = (float*)(sraw + 107008);
    float*  cbuf_s= (float*)(sraw + 108032);
    float*  rowsum_s = (float*)(sraw + 108544);
    __half* ypart = (__half*)(sraw + 108672);  // 32 x 64 (stride 72)
    const int tile = blockIdx.x, batch = blockIdx.y, tid = threadIdx.x;

    const __half* nfg = g_nfh + (size_t)batch * N1 * 64;
    for (int e = tid; e < 4096; e += 512)
        cp16(sptr(nf_s + (e >> 3) * 72 + (e & 7) * 8), nfg + e * 8);
    for (int e = tid; e < 512; e += 512)
        cp16(sptr(Wh0 + (e >> 3) * 72 + (e & 7) * 8), g_Wh + e * 8);
    if (tid < 32) cp16(sptr(cbuf_s + tid * 4), g_cbuf + tid * 4);
    CP_COMMIT; CP_WAIT0;
    __syncthreads();

    const int w = tid >> 5, lane = tid & 31;
    const int band = w >> 3, colg = w & 7;
    const int lq = lane >> 2, lr = lane & 3;
    const int rl0 = band * 16 + lq;
    const int rg0 = tile * 32 + rl0, rg1 = rg0 + 8;
    const int n0 = colg * 8;

    // diag ownership (single slot per row)
    const bool eq0 = ((rg0 >> 6) == colg) && (((rg0 >> 1) & 3) == lr);
    const bool eq1 = ((rg1 >> 6) == colg) && (((rg1 >> 1) & 3) == lr);
    const int key0 = (((rg0 & 63) >> 3) << 1) | (rg0 & 1);
    const int key1 = (((rg1 & 63) >> 3) << 1) | (rg1 & 1);

    // ---- scores (32x512) + z1 fold ----
    float acc[8][4];
#pragma unroll
    for (int t = 0; t < 8; t++) { acc[t][0] = acc[t][1] = acc[t][2] = acc[t][3] = 0.f; }
    float va[4] = {0.f, 0.f, 0.f, 0.f};
    {
        unsigned zp0 = 0, zp1 = 0, zp2 = 0, zp3 = 0;
#pragma unroll
        for (int ks = 0; ks < 4; ks++) {
            const int k0 = ks * 16;
            unsigned a0, a1, a2, a3; ldsm4h(a0, a1, a2, a3, nf_s, tile * 32 + band * 16, k0, 72);
#pragma unroll
            for (int tt = 0; tt < 4; tt++) {
                unsigned b0, b1, b2v, b3v;
                ldsm4h_n(b0, b1, b2v, b3v, nf_s, colg * 64 + tt * 16, k0, 72);
                mma_f16(acc[tt * 2],     a0, a1, a2, a3, b0, b1);
                mma_f16(acc[tt * 2 + 1], a0, a1, a2, a3, b2v, b3v);
            }
            if ((ks & 1) == 0) {
                ldsm4h_nk(zp0, zp1, zp2, zp3, Wh0, n0, k0, 72);
                mma_f16(va, a0, a1, a2, a3, zp0, zp1);
            } else {
                mma_f16(va, a0, a1, a2, a3, zp2, zp3);
            }
        }
    }
    __syncthreads();

    // ---- leaky + exp + partial sums (compare-free) ----
    float s0 = 0.f, s1 = 0.f;
#pragma unroll
    for (int t = 0; t < 8; t++) {
#pragma unroll
        for (int j = 0; j < 2; j++) {
            float v = acc[t][j];
            v = v > 0.f ? v : SLOPE * v;
            float e0 = __expf(v); acc[t][j] = e0; s0 += e0;
            float u = acc[t][2 + j];
            u = u > 0.f ? u : SLOPE * u;
            float e1 = __expf(u); acc[t][2 + j] = e1; s1 += e1;
        }
    }
    if (eq0) {
#pragma unroll
        for (int t = 0; t < 8; t++)
#pragma unroll
            for (int j = 0; j < 2; j++)
                if (((t << 1) | j) == key0) { s0 -= acc[t][j]; acc[t][j] = 0.f; }
    }
    if (eq1) {
#pragma unroll
        for (int t = 0; t < 8; t++)
#pragma unroll
            for (int j = 0; j < 2; j++)
                if (((t << 1) | j) == key1) { s1 -= acc[t][2 + j]; acc[t][2 + j] = 0.f; }
    }
    s0 += __shfl_xor_sync(~0u, s0, 1); s0 += __shfl_xor_sync(~0u, s0, 2);
    s1 += __shfl_xor_sync(~0u, s1, 1); s1 += __shfl_xor_sync(~0u, s1, 2);
    if (lr == 0) { reds[rl0 * 8 + colg] = s0; reds[(rl0 + 8) * 8 + colg] = s1; }
    __syncthreads();
    float lo0, hi0, lo1, hi1;
    {
        float4 ra = *(const float4*)(reds + rl0 * 8);
        float4 rb4 = *(const float4*)(reds + rl0 * 8 + 4);
        float4 rc = *(const float4*)(reds + (rl0 + 8) * 8);
        float4 rd4 = *(const float4*)(reds + (rl0 + 8) * 8 + 4);
        lo0 = ra.x + ra.y + ra.z + ra.w;   hi0 = rb4.x + rb4.y + rb4.z + rb4.w;
        lo1 = rc.x + rc.y + rc.z + rc.w;   hi1 = rd4.x + rd4.y + rd4.z + rd4.w;
    }
    const float T0 = lo0 + hi0, T1 = lo1 + hi1;
    const float inv0 = 1.f / T0, inv1 = 1.f / T1;
    const bool rlo = (tile < 8);
    if (colg == 0 && lr == 0) {
        rowsum_s[rl0]     = (rlo ? lo0 + 0.7f * hi0 : 0.7f * lo0 + hi0) * inv0 + 1.f;
        rowsum_s[rl0 + 8] = (rlo ? lo1 + 0.7f * hi1 : 0.7f * lo1 + hi1) * inv1 + 1.f;
    }
    const float msk = (rlo != (colg < 4)) ? 0.7f : 1.0f;
    if (eq0) {
#pragma unroll
        for (int t = 0; t < 8; t++)
#pragma unroll
            for (int j = 0; j < 2; j++)
                if (((t << 1) | j) == key0) acc[t][j] = T0;
    }
    if (eq1) {
#pragma unroll
        for (int t = 0; t < 8; t++)
#pragma unroll
            for (int j = 0; j < 2; j++)
                if (((t << 1) | j) == key1) acc[t][2 + j] = T1;
    }
    const float m0s = inv0 * msk, m1s = inv1 * msk;

#pragma unroll
    for (int tp = 0; tp < 4; tp++) {
        const int ct = colg * 64 + tp * 16;
        stsm4h(adj_s, band * 16, ct, 520,
               h2u(acc[2*tp][0] * m0s,   acc[2*tp][1] * m0s),
               h2u(acc[2*tp][2] * m1s,   acc[2*tp][3] * m1s),
               h2u(acc[2*tp+1][0] * m0s, acc[2*tp+1][1] * m0s),
               h2u(acc[2*tp+1][2] * m1s, acc[2*tp+1][3] * m1s));
    }
    __syncthreads();

    // ---- warps 0-3: y = adj @ nf, 32x32 tiles, k-split (kh = w>>1);
    //      warps 4-15: adj -> global ----
    float yacc[2][4][4];
#pragma unroll
    for (int rr = 0; rr < 2; rr++)
#pragma unroll
        for (int t = 0; t < 4; t++) { yacc[rr][t][0] = yacc[rr][t][1] = yacc[rr][t][2] = yacc[rr][t][3] = 0.f; }
    const int ych = (w & 1) * 32, kh = (w >> 1) & 1;
    if (w < 4) {
        const int kbase = kh * 256;
#pragma unroll 2
        for (int kp = 0; kp < 256; kp += 32) {
            const int k0 = kbase + kp;
            unsigned a0, a1, a2, a3; ldsm4h(a0, a1, a2, a3, adj_s, 0,  k0, 520);
            unsigned e0, e1, e2, e3; ldsm4h(e0, e1, e2, e3, adj_s, 0,  k0 + 16, 520);
            unsigned f0, f1, f2, f3; ldsm4h(f0, f1, f2, f3, adj_s, 16, k0, 520);
            unsigned g0, g1, g2, g3; ldsm4h(g0, g1, g2, g3, adj_s, 16, k0 + 16, 520);
#pragma unroll
            for (int nt = 0; nt < 4; nt++) {
                unsigned b0, b1, b2v, b3v;
                ldsm4h_t(b0, b1, b2v, b3v, nf_s, k0, ych + nt * 8, 72);
                mma_f16(yacc[0][nt], a0, a1, a2, a3, b0, b1);
                mma_f16(yacc[0][nt], e0, e1, e2, e3, b2v, b3v);
                mma_f16(yacc[1][nt], f0, f1, f2, f3, b0, b1);
                mma_f16(yacc[1][nt], g0, g1, g2, g3, b2v, b3v);
            }
        }
    } else {
        const size_t gb = ((size_t)batch * N1 + tile * 32) * N1;
        for (int e = tid - 128; e < 2048; e += 384) {
            const int r = e >> 6, c8 = e & 63;
            *(uint4*)(g_adjh + gb + (size_t)r * N1 + c8 * 8) =
                *(const uint4*)(adj_s + r * 520 + c8 * 8);
        }
    }
    __syncthreads();   // y MMAs done reading nf_s / adj_s

    // ---- kh=1 warps stage partials; fetch th1' ----
    __half* y_s  = nf_s;
    __half* Wh1s = nf_s + 2304;
    if (w >= 2 && w < 4) {
#pragma unroll
        for (int rr = 0; rr < 2; rr++)
#pragma unroll
            for (int cc = 0; cc < 2; cc++)
                stsm4h(ypart, rr * 16, ych + cc * 16, 72,
                       h2u(yacc[rr][cc*2][0], yacc[rr][cc*2][1]),
                       h2u(yacc[rr][cc*2][2], yacc[rr][cc*2][3]),
                       h2u(yacc[rr][cc*2+1][0], yacc[rr][cc*2+1][1]),
                       h2u(yacc[rr][cc*2+1][2], yacc[rr][cc*2+1][3]));
    }
    for (int e = tid; e < 512; e += 512)
        cp16(sptr(Wh1s + (e >> 3) * 72 + (e & 7) * 8), g_Wh + 64 * 64 + e * 8);
    CP_COMMIT;
    __syncthreads();   // partials visible

    // ---- kh=0 warps combine + stage final y ----
    if (w < 2) {
#pragma unroll
        for (int rr = 0; rr < 2; rr++)
#pragma unroll
            for (int cc = 0; cc < 2; cc++) {
                unsigned p0, p1, p2, p3;
                ldsm4h(p0, p1, p2, p3, ypart, rr * 16, ych + cc * 16, 72);
                const __half2 h0 = *reinterpret_cast<__half2*>(&p0);
                const __half2 h1 = *reinterpret_cast<__half2*>(&p1);
                const __half2 h2 = *reinterpret_cast<__half2*>(&p2);
                const __half2 h3 = *reinterpret_cast<__half2*>(&p3);
                yacc[rr][cc*2][0]   += __low2float(h0); yacc[rr][cc*2][1]   += __high2float(h0);
                yacc[rr][cc*2][2]   += __low2float(h1); yacc[rr][cc*2][3]   += __high2float(h1);
                yacc[rr][cc*2+1][0] += __low2float(h2); yacc[rr][cc*2+1][1] += __high2float(h2);
                yacc[rr][cc*2+1][2] += __low2float(h3); yacc[rr][cc*2+1][3] += __high2float(h3);
                stsm4h(y_s, rr * 16, ych + cc * 16, 72,
                       h2u(yacc[rr][cc*2][0], yacc[rr][cc*2][1]),
                       h2u(yacc[rr][cc*2][2], yacc[rr][cc*2][3]),
                       h2u(yacc[rr][cc*2+1][0], yacc[rr][cc*2+1][1]),
                       h2u(yacc[rr][cc*2+1][2], yacc[rr][cc*2+1][3]));
            }
    }
    CP_WAIT0;
    __syncthreads();   // y_s + Wh1s ready

    // ---- t = va + y@th1'^T + rowsum*c1 + c0 ----
    float at[4] = {0.f, 0.f, 0.f, 0.f};
    {
        unsigned zp0 = 0, zp1 = 0, zp2 = 0, zp3 = 0;
#pragma unroll
        for (int ks = 0; ks < 4; ks++) {
            const int k0 = ks * 16;
            unsigned a0, a1, a2, a3; ldsm4h(a0, a1, a2, a3, y_s, band * 16, k0, 72);
            if ((ks & 1) == 0) {
                ldsm4h_nk(zp0, zp1, zp2, zp3, Wh1s, n0, k0, 72);
                mma_f16(at, a0, a1, a2, a3, zp0, zp1);
            } else {
                mma_f16(at, a0, a1, a2, a3, zp2, zp3);
            }
        }
    }
    const size_t rb = (size_t)batch * N1 + tile * 32 + rl0;
    const int cA = n0 + lr * 2;
    const float c0a = cbuf_s[cA], c0b = cbuf_s[cA + 1];
    const float c1a = cbuf_s[64 + cA], c1b = cbuf_s[64 + cA + 1];
    const float rs0 = rowsum_s[rl0], rs1 = rowsum_s[rl0 + 8];
    *(__half2*)(g_th + rb * 64 + cA) =
        __floats2half2_rn(va[0] + at[0] + rs0 * c1a + c0a,
                          va[1] + at[1] + rs0 * c1b + c0b);
    *(__half2*)(g_th + (rb + 8) * 64 + cA) =
        __floats2half2_rn(va[2] + at[2] + rs1 * c1a + c0a,
                          va[3] + at[3] + rs1 * c1b + c0b);
}

// ---------------- K4: op = adj @ t + bias, 128-row tiles, 32x32 k-split ------
__global__ void __launch_bounds__(512, 2) k_out(const float* __restrict__ th0b,
                                                const float* __restrict__ th1b) {
    extern __shared__ char sraw[];
    __half* t_s = (__half*)sraw;
    __half* cbA = (__half*)(sraw + 73728);
    __half* cbB = (__half*)(sraw + 92160);
    __half* pst = cbA;                       // 8 * 32*40 halves = 20480 B
    const int tile = blockIdx.x, batch = blockIdx.y, tid = threadIdx.x;

    const __half* tg = g_th + (size_t)batch * N1 * 64;
    const __half* ag = g_adjh + ((size_t)batch * N1 + tile * 128) * N1;
    for (int e = tid; e < 4096; e += 512)
        cp16(sptr(t_s + (e >> 3) * 72 + (e & 7) * 8), tg + e * 8);
    for (int e = tid; e < 1024; e += 512) {
        const int r = e >> 3, c8 = e & 7;
        cp16(sptr(cbA + r * 72 + c8 * 8), ag + (size_t)r * N1 + c8 * 8);
    }
    CP_COMMIT;

    const int w = tid >> 5, lane = tid & 31;
    const int kh = w >> 3, sub = w & 7;
    const int rband = sub >> 1, chalf = sub & 1;
    const int lq = lane >> 2, lr = lane & 3;
    float acc[2][4][4];
#pragma unroll
    for (int rr = 0; rr < 2; rr++)
#pragma unroll
        for (int t = 0; t < 4; t++) { acc[rr][t][0] = acc[rr][t][1] = acc[rr][t][2] = acc[rr][t][3] = 0.f; }

    for (int ch = 0; ch < 8; ch++) {
        __half* cb = (ch & 1) ? cbB : cbA;
        if (ch < 7) {
            __half* nb = (ch & 1) ? cbA : cbB;
            for (int e = tid; e < 1024; e += 512) {
                const int r = e >> 3, c8 = e & 7;
                cp16(sptr(nb + r * 72 + c8 * 8), ag + (size_t)r * N1 + (ch + 1) * 64 + c8 * 8);
            }
            CP_COMMIT; CP_WAIT1;
        } else {
            CP_WAIT0;
        }
        __syncthreads();
        if ((ch >> 2) == kh) {
#pragma unroll
            for (int kp = 0; kp < 64; kp += 32) {
                unsigned a0, a1, a2, a3; ldsm4h(a0, a1, a2, a3, cb, rband * 32,      kp, 72);
                unsigned e0, e1, e2, e3; ldsm4h(e0, e1, e2, e3, cb, rband * 32,      kp + 16, 72);
                unsigned f0, f1, f2, f3; ldsm4h(f0, f1, f2, f3, cb, rband * 32 + 16, kp, 72);
                unsigned g0, g1, g2, g3; ldsm4h(g0, g1, g2, g3, cb, rband * 32 + 16, kp + 16, 72);
#pragma unroll
                for (int nt = 0; nt < 4; nt++) {
                    unsigned b0, b1, b2v, b3v;
                    ldsm4h_t(b0, b1, b2v, b3v, t_s, ch * 64 + kp, chalf * 32 + nt * 8, 72);
                    mma_f16(acc[0][nt], a0, a1, a2, a3, b0, b1);
                    mma_f16(acc[0][nt], e0, e1, e2, e3, b2v, b3v);
                    mma_f16(acc[1][nt], f0, f1, f2, f3, b0, b1);
                    mma_f16(acc[1][nt], g0, g1, g2, g3, b2v, b3v);
                }
            }
        }
        __syncthreads();
    }

    if (kh == 1) {
        __half* pt = pst + sub * 1280;
#pragma unroll
        for (int rr = 0; rr < 2; rr++)
#pragma unroll
            for (int cc = 0; cc < 2; cc++)
                stsm4h(pt, rr * 16, cc * 16, 40,
                       h2u(acc[rr][cc*2][0], acc[rr][cc*2][1]),
                       h2u(acc[rr][cc*2][2], acc[rr][cc*2][3]),
                       h2u(acc[rr][cc*2+1][0], acc[rr][cc*2+1][1]),
                       h2u(acc[rr][cc*2+1][2], acc[rr][cc*2+1][3]));
    }
    __syncthreads();
    if (kh == 0) {
        __half* pt = pst + sub * 1280;
#pragma unroll
        for (int rr = 0; rr < 2; rr++)
#pragma unroll
            for (int cc = 0; cc < 2; cc++) {
                unsigned p0, p1, p2, p3;
                ldsm4h(p0, p1, p2, p3, pt, rr * 16, cc * 16, 40);
                const __half2 h0 = *reinterpret_cast<__half2*>(&p0);
                const __half2 h1 = *reinterpret_cast<__half2*>(&p1);
                const __half2 h2 = *reinterpret_cast<__half2*>(&p2);
                const __half2 h3 = *reinterpret_cast<__half2*>(&p3);
                acc[rr][cc*2][0]   += __low2float(h0); acc[rr][cc*2][1]   += __high2float(h0);
                acc[rr][cc*2][2]   += __low2float(h1); acc[rr][cc*2][3]   += __high2float(h1);
                acc[rr][cc*2+1][0] += __low2float(h2); acc[rr][cc*2+1][1] += __high2float(h2);
                acc[rr][cc*2+1][2] += __low2float(h3); acc[rr][cc*2+1][3] += __high2float(h3);
            }
        const size_t rbase = (size_t)batch * N1 + tile * 128 + rband * 32;
#pragma unroll
        for (int rr = 0; rr < 2; rr++) {
            const size_t rb = rbase + rr * 16 + lq;
#pragma unroll
            for (int nt = 0; nt < 4; nt++) {
                const int cA = chalf * 32 + nt * 8 + lr * 2;
                const float bc0 = __ldg(th0b + cA) + __ldg(th1b + cA);
                const float bc1 = __ldg(th0b + cA + 1) + __ldg(th1b + cA + 1);
                *(__half2*)(g_oph + rb * 64 + cA) =
                    __floats2half2_rn(acc[rr][nt][0] + bc0, acc[rr][nt][1] + bc1);
                *(__half2*)(g_oph + (rb + 8) * 64 + cA) =
                    __floats2half2_rn(acc[rr][nt][2] + bc0, acc[rr][nt][3] + bc1);
            }
        }
    }
}

// ---------------- K5: BN1 affine + leaky + mean pool (half2 reads) -----------
__global__ void k_final(float* __restrict__ out) {
    const int idx = blockIdx.x * 256 + threadIdx.x;
    const int c2 = idx & 31;
    const int n = (idx >> 5) & 255;
    const int b = idx >> 13;
    const float a0 = g_coef[1][0][c2 * 2], a1 = g_coef[1][0][c2 * 2 + 1];
    const float d0 = g_coef[1][1][c2 * 2], d1 = g_coef[1][1][c2 * 2 + 1];
    float s0 = 0.f, s1 = 0.f;
#pragma unroll 2
    for (int l = 0; l < LWIN; l++)
#pragma unroll
        for (int m = 0; m < 2; m++) {
            __half2 h = *(const __half2*)(g_oph +
                (((size_t)(b * LWIN + l) * N1 + m * NNODE + n) << 6) + c2 * 2);
            float2 f = __half22float2(h);
            float v0 = a0 * f.x + d0; s0 += (v0 > 0.f) ? v0 : SLOPE * v0;
            float v1 = a1 * f.y + d1; s1 += (v1 > 0.f) ? v1 : SLOPE * v1;
        }
    *(float2*)(out + (((size_t)(b * NNODE + n)) << 6) + c2 * 2) =
        make_float2(s0 * (1.f / 32.f), s1 * (1.f / 32.f));
}

// ---------------- launch ------------------------------------------------------
extern "C" void kernel_launch(void* const* d_in, const int* in_sizes, int n_in,
                              void* d_out, int out_size) {
    const float* x    = (const float*)d_in[0];
    const float* w2   = (const float*)d_in[1];
    const float* b2   = (const float*)d_in[2];
    const float* bn0w = (const float*)d_in[3];
    const float* bn0b = (const float*)d_in[4];
    const float* th0w = (const float*)d_in[5];
    const float* th0b = (const float*)d_in[6];
    const float* th1w = (const float*)d_in[7];
    const float* th1b = (const float*)d_in[8];
    const float* bn1w = (const float*)d_in[9];
    const float* bn1b = (const float*)d_in[10];
    float* out = (float*)d_out;

    const int SMEM_ADJ = 113280;   // + ypart
    const int SMEM_OUT = 110592;
    cudaFuncSetAttribute(k_adj, cudaFuncAttributeMaxDynamicSharedMemorySize, SMEM_ADJ);
    cudaFuncSetAttribute(k_out, cudaFuncAttributeMaxDynamicSharedMemorySize, SMEM_OUT);

    k_nf<<<dim3(8, BP), 256>>>(x, w2, b2);
    k_stats_p1<<<BP, 256>>>(0);
    k_p2prep<<<1, 128>>>(bn0w, bn0b, th0w, th1w);
    k_adj<<<dim3(16, BP), 512, SMEM_ADJ>>>();
    k_out<<<dim3(4, BP), 512, SMEM_OUT>>>(th0b, th1b);
    k_stats_p1<<<BP, 256>>>(1);
    k_stats_p2<<<1, 64>>>(bn1w, bn1b, 1);
    k_final<<<512, 256>>>(out);
}

// round 16
// speedup vs baseline: 1.0384x; 1.0384x over previous
#include <cuda_runtime.h>
#include <cuda_fp16.h>
#include <math.h>
#include <stdint.h>

#define BATCH   16
#define SEQ     17
#define NNODE   256
#define FDIM    64
#define LWIN    16
#define BP      256         // BATCH*LWIN
#define N1      512
#define OUTD    64
#define NTOT    (BP*N1)
#define SLOPE   0.01f

// ---------------- scratch ----------------------------------------------------
__device__ __half g_nfh [(size_t)BP*N1*FDIM];
__device__ __half g_adjh[(size_t)BP*N1*N1];     // 134 MB
__device__ __half g_th  [(size_t)BP*N1*FDIM];
__device__ __half g_oph [(size_t)BP*N1*OUTD];
__device__ float  g_part[2][BP][128];
__device__ float  g_coef[2][2][64];             // [1] used by k_final
__device__ __half g_Wh  [128*64];               // rows 0-63: th0*a ; 64-127: th1*a
__device__ float  g_cbuf[128];                  // [0..64): th0@d ; [64..128): th1@d

// ---------------- helpers ----------------------------------------------------
__device__ __forceinline__ uint32_t sptr(const void* p) {
    return (uint32_t)__cvta_generic_to_shared(p);
}
__device__ __forceinline__ void cp16(uint32_t d, const void* s) {
    asm volatile("cp.async.cg.shared.global [%0],[%1],16;" :: "r"(d), "l"(s));
}
#define CP_COMMIT asm volatile("cp.async.commit_group;")
#define CP_WAIT0  asm volatile("cp.async.wait_group 0;")
#define CP_WAIT1  asm volatile("cp.async.wait_group 1;")

__device__ __forceinline__ void mma_f16(float c[4], unsigned a0, unsigned a1,
                                        unsigned a2, unsigned a3,
                                        unsigned b0, unsigned b1) {
    asm volatile(
        "mma.sync.aligned.m16n8k16.row.col.f32.f16.f16.f32 "
        "{%0,%1,%2,%3},{%4,%5,%6,%7},{%8,%9},{%0,%1,%2,%3};"
        : "+f"(c[0]), "+f"(c[1]), "+f"(c[2]), "+f"(c[3])
        : "r"(a0), "r"(a1), "r"(a2), "r"(a3), "r"(b0), "r"(b1));
}
// A-fragment (16x16), row-major [m][k]
__device__ __forceinline__ void ldsm4h(unsigned& r0, unsigned& r1, unsigned& r2, unsigned& r3,
                                       const __half* base, int row0, int k0, int stride) {
    const int lane = threadIdx.x & 31;
    uint32_t a = sptr(base + (row0 + (lane & 15)) * stride + k0 + ((lane >> 4) << 3));
    asm volatile("ldmatrix.sync.aligned.m8n8.x4.shared.b16 {%0,%1,%2,%3},[%4];"
                 : "=r"(r0), "=r"(r1), "=r"(r2), "=r"(r3) : "r"(a));
}
// B-fragments from [n][k] storage: TWO adjacent n-tiles (n0, n0+8) in one x4
__device__ __forceinline__ void ldsm4h_n(unsigned& r0, unsigned& r1, unsigned& r2, unsigned& r3,
                                         const __half* base, int n0, int k0, int stride) {
    const int lane = threadIdx.x & 31;
    uint32_t a = sptr(base + (n0 + (lane & 7) + ((lane >> 4) << 3)) * stride
                      + k0 + (((lane >> 3) & 1) << 3));
    asm volatile("ldmatrix.sync.aligned.m8n8.x4.shared.b16 {%0,%1,%2,%3},[%4];"
                 : "=r"(r0), "=r"(r1), "=r"(r2), "=r"(r3) : "r"(a));
}
// B-fragments from [n][k] storage: ONE n-tile, TWO k-steps (k0, k0+16) in one x4
__device__ __forceinline__ void ldsm4h_nk(unsigned& r0, unsigned& r1, unsigned& r2, unsigned& r3,
                                          const __half* base, int n0, int k0, int stride) {
    const int lane = threadIdx.x & 31;
    uint32_t a = sptr(base + (n0 + (lane & 7)) * stride
                      + k0 + (((lane >> 3) & 1) << 3) + ((lane >> 4) << 4));
    asm volatile("ldmatrix.sync.aligned.m8n8.x4.shared.b16 {%0,%1,%2,%3},[%4];"
                 : "=r"(r0), "=r"(r1), "=r"(r2), "=r"(r3) : "r"(a));
}
// B-fragments from [k][n] storage: k-steps k0 and k0+16 of one n-tile (x4 trans)
__device__ __forceinline__ void ldsm4h_t(unsigned& r0, unsigned& r1, unsigned& r2, unsigned& r3,
                                         const __half* base, int k0, int n0, int stride) {
    const int lane = threadIdx.x & 31;
    uint32_t a = sptr(base + (k0 + lane) * stride + n0);
    asm volatile("ldmatrix.sync.aligned.m8n8.x4.trans.shared.b16 {%0,%1,%2,%3},[%4];"
                 : "=r"(r0), "=r"(r1), "=r"(r2), "=r"(r3) : "r"(a));
}
// Store a 16x16 accumulator tile (as half) via stmatrix x4. Same addr map as ldsm4h.
__device__ __forceinline__ void stsm4h(__half* base, int row0, int n0, int stride,
                                       unsigned p0, unsigned p1, unsigned p2, unsigned p3) {
    const int lane = threadIdx.x & 31;
    uint32_t a = sptr(base + (row0 + (lane & 15)) * stride + n0 + ((lane >> 4) << 3));
    asm volatile("stmatrix.sync.aligned.m8n8.x4.shared.b16 [%0], {%1,%2,%3,%4};"
                 :: "r"(a), "r"(p0), "r"(p1), "r"(p2), "r"(p3) : "memory");
}
__device__ __forceinline__ unsigned h2u(float a, float b) {
    __half2 h = __floats2half2_rn(a, b);
    return *reinterpret_cast<unsigned*>(&h);
}

// ---------------- K1: nf = gather(X) @ w2^T + b2 ----------------------------
__global__ void __launch_bounds__(256) k_nf(const float* __restrict__ x,
                                            const float* __restrict__ w2,
                                            const float* __restrict__ b2) {
    __shared__ __half xh[64 * 72];
    __shared__ __half wh[64 * 72];
    const int tile = blockIdx.x, batch = blockIdx.y, tid = threadIdx.x;
    const int b = batch / LWIN, l = batch % LWIN;

    for (int e = tid; e < 1024; e += 256) {
        const int row = e >> 4, c4 = e & 15;
        const int r = tile * 64 + row, m = r >> 8, n = r & 255;
        float4 xv = *(const float4*)(x + ((size_t)(b * SEQ + l + m) * NNODE + n) * FDIM + c4 * 4);
        *(__half2*)(xh + row * 72 + c4 * 4)     = __floats2half2_rn(xv.x, xv.y);
        *(__half2*)(xh + row * 72 + c4 * 4 + 2) = __floats2half2_rn(xv.z, xv.w);
        float4 wv = *(const float4*)(w2 + row * 64 + c4 * 4);
        *(__half2*)(wh + row * 72 + c4 * 4)     = __floats2half2_rn(wv.x, wv.y);
        *(__half2*)(wh + row * 72 + c4 * 4 + 2) = __floats2half2_rn(wv.z, wv.w);
    }
    __syncthreads();

    const int w = tid >> 5, lane = tid & 31;
    const int band = w >> 1, colg = w & 1;
    const int lq = lane >> 2, lr = lane & 3;
    float acc[4][4];
#pragma unroll
    for (int t = 0; t < 4; t++) { acc[t][0] = acc[t][1] = acc[t][2] = acc[t][3] = 0.f; }
#pragma unroll
    for (int ks = 0; ks < 4; ks++) {
        const int k0 = ks * 16;
        unsigned a0, a1, a2, a3; ldsm4h(a0, a1, a2, a3, xh, band * 16, k0, 72);
#pragma unroll
        for (int tt = 0; tt < 2; tt++) {
            unsigned b0, b1, b2v, b3v;
            ldsm4h_n(b0, b1, b2v, b3v, wh, colg * 32 + tt * 16, k0, 72);
            mma_f16(acc[tt * 2],     a0, a1, a2, a3, b0, b1);
            mma_f16(acc[tt * 2 + 1], a0, a1, a2, a3, b2v, b3v);
        }
    }
    const size_t ob = ((size_t)batch * N1 + tile * 64 + band * 16 + lq) * 64;
#pragma unroll
    for (int t = 0; t < 4; t++) {
        const int c = colg * 32 + t * 8 + lr * 2;
        const float bb0 = __ldg(b2 + c), bb1 = __ldg(b2 + c + 1);
        *(__half2*)(g_nfh + ob + c) = __floats2half2_rn(acc[t][0] + bb0, acc[t][1] + bb1);
        *(__half2*)(g_nfh + ob + (size_t)8 * 64 + c) = __floats2half2_rn(acc[t][2] + bb0, acc[t][3] + bb1);
    }
}

// ---------------- BN stats (streaming, half sources) --------------------------
__global__ void k_stats_p1(int which) {
    const int batch = blockIdx.x, tid = threadIdx.x;
    const int c = tid & 63, rg = tid >> 6;
    const __half* p = ((which == 0) ? g_nfh : g_oph) + (size_t)batch * N1 * 64;
    float s = 0.f, q = 0.f;
    for (int r = rg * 128; r < rg * 128 + 128; r++) {
        float v = __half2float(p[(size_t)r * 64 + c]);
        s += v; q += v * v;
    }
    __shared__ float sm[256], qm[256];
    sm[tid] = s; qm[tid] = q;
    __syncthreads();
    if (tid < 64) {
        g_part[which][batch][tid]      = sm[tid] + sm[tid + 64] + sm[tid + 128] + sm[tid + 192];
        g_part[which][batch][tid + 64] = qm[tid] + qm[tid + 64] + qm[tid + 128] + qm[tid + 192];
    }
}
__global__ void k_stats_p2(const float* __restrict__ w, const float* __restrict__ bb, int which) {
    const int c = threadIdx.x;
    float s = 0.f, q = 0.f;
    for (int b2 = 0; b2 < BP; b2++) { s += g_part[which][b2][c]; q += g_part[which][b2][c + 64]; }
    const float mu  = s / (float)NTOT;
    const float var = q / (float)NTOT - mu * mu;
    const float a   = w[c] * rsqrtf(var + 1e-5f);
    g_coef[which][0][c] = a;
    g_coef[which][1][c] = bb[c] - mu * a;
}

// ---------------- K1b: BN0 coefs + theta fold, fused (1 CTA, 128 thr) --------
__global__ void k_p2prep(const float* __restrict__ bn0w, const float* __restrict__ bn0b,
                         const float* __restrict__ th0w, const float* __restrict__ th1w) {
    __shared__ float ca[64], cd[64];
    const int tid = threadIdx.x;    // 128
    if (tid < 64) {
        float s = 0.f, q = 0.f;
        for (int b2 = 0; b2 < BP; b2++) { s += g_part[0][b2][tid]; q += g_part[0][b2][tid + 64]; }
        const float mu  = s / (float)NTOT;
        const float var = q / (float)NTOT - mu * mu;
        const float a   = bn0w[tid] * rsqrtf(var + 1e-5f);
        ca[tid] = a; cd[tid] = bn0b[tid] - mu * a;
    }
    __syncthreads();
    const int n = tid;
    const float* wr = (n < 64) ? (th0w + n * 64) : (th1w + (n - 64) * 64);
    float c = 0.f;
#pragma unroll 8
    for (int k = 0; k < 64; k++) {
        const float wv = wr[k];
        g_Wh[n * 64 + k] = __float2half(wv * ca[k]);
        c += wv * cd[k];
    }
    g_cbuf[n] = c;
}

// ---------------- K3: two 32-row tiles per CTA; adj + z1 fold + y + t --------
// smem bytes: nf_s[512*72]h @0 (persistent across both tiles)
//             adj_s[32*520]h @73728 (Wh0 / y_s / Wh1s alias its head per phase)
//             reds @107008 | cbuf_s @108032 | rowsum_s @108544
__global__ void __launch_bounds__(512, 2) k_adj() {
    extern __shared__ char sraw[];
    __half* nf_s  = (__half*)sraw;
    __half* adj_s = (__half*)(sraw + 73728);
    __half* Wh0   = adj_s;                     // consumed before softmax writes
    float*  reds  = (float*)(sraw + 107008);
    float*  cbuf_s= (float*)(sraw + 108032);
    float*  rowsum_s = (float*)(sraw + 108544);
    const int batch = blockIdx.y, tid = threadIdx.x;

    // persistent fills: nf (full 512x64) + cbuf
    const __half* nfg = g_nfh + (size_t)batch * N1 * 64;
    for (int e = tid; e < 4096; e += 512)
        cp16(sptr(nf_s + (e >> 3) * 72 + (e & 7) * 8), nfg + e * 8);
    if (tid < 32) cp16(sptr(cbuf_s + tid * 4), g_cbuf + tid * 4);

    const int w = tid >> 5, lane = tid & 31;
    const int band = w >> 3, colg = w & 7;
    const int lq = lane >> 2, lr = lane & 3;
    const int rl0 = band * 16 + lq;
    const int n0 = colg * 8;

    for (int sub = 0; sub < 2; sub++) {
        const int tile = blockIdx.x * 2 + sub;
        if (sub) __syncthreads();              // protect adj_s (y_s/Wh1s) from prior tile
        // per-tile Wh0 fill into adj_s head
        for (int e = tid; e < 512; e += 512)
            cp16(sptr(Wh0 + (e >> 3) * 72 + (e & 7) * 8), g_Wh + e * 8);
        CP_COMMIT; CP_WAIT0;
        __syncthreads();

        const int rg0 = tile * 32 + rl0, rg1 = rg0 + 8;
        const bool eq0 = ((rg0 >> 6) == colg) && (((rg0 >> 1) & 3) == lr);
        const bool eq1 = ((rg1 >> 6) == colg) && (((rg1 >> 1) & 3) == lr);
        const int key0 = (((rg0 & 63) >> 3) << 1) | (rg0 & 1);
        const int key1 = (((rg1 & 63) >> 3) << 1) | (rg1 & 1);

        // ---- scores (32x512) + z1 fold ----
        float acc[8][4];
#pragma unroll
        for (int t = 0; t < 8; t++) { acc[t][0] = acc[t][1] = acc[t][2] = acc[t][3] = 0.f; }
        float va[4] = {0.f, 0.f, 0.f, 0.f};
        {
            unsigned zp0 = 0, zp1 = 0, zp2 = 0, zp3 = 0;
#pragma unroll
            for (int ks = 0; ks < 4; ks++) {
                const int k0 = ks * 16;
                unsigned a0, a1, a2, a3; ldsm4h(a0, a1, a2, a3, nf_s, tile * 32 + band * 16, k0, 72);
#pragma unroll
                for (int tt = 0; tt < 4; tt++) {
                    unsigned b0, b1, b2v, b3v;
                    ldsm4h_n(b0, b1, b2v, b3v, nf_s, colg * 64 + tt * 16, k0, 72);
                    mma_f16(acc[tt * 2],     a0, a1, a2, a3, b0, b1);
                    mma_f16(acc[tt * 2 + 1], a0, a1, a2, a3, b2v, b3v);
                }
                if ((ks & 1) == 0) {
                    ldsm4h_nk(zp0, zp1, zp2, zp3, Wh0, n0, k0, 72);
                    mma_f16(va, a0, a1, a2, a3, zp0, zp1);
                } else {
                    mma_f16(va, a0, a1, a2, a3, zp2, zp3);
                }
            }
        }
        __syncthreads();

        // ---- leaky + exp + partial sums (compare-free) ----
        float s0 = 0.f, s1 = 0.f;
#pragma unroll
        for (int t = 0; t < 8; t++) {
#pragma unroll
            for (int j = 0; j < 2; j++) {
                float v = acc[t][j];
                v = v > 0.f ? v : SLOPE * v;
                float e0 = __expf(v); acc[t][j] = e0; s0 += e0;
                float u = acc[t][2 + j];
                u = u > 0.f ? u : SLOPE * u;
                float e1 = __expf(u); acc[t][2 + j] = e1; s1 += e1;
            }
        }
        if (eq0) {
#pragma unroll
            for (int t = 0; t < 8; t++)
#pragma unroll
                for (int j = 0; j < 2; j++)
                    if (((t << 1) | j) == key0) { s0 -= acc[t][j]; acc[t][j] = 0.f; }
        }
        if (eq1) {
#pragma unroll
            for (int t = 0; t < 8; t++)
#pragma unroll
                for (int j = 0; j < 2; j++)
                    if (((t << 1) | j) == key1) { s1 -= acc[t][2 + j]; acc[t][2 + j] = 0.f; }
        }
        s0 += __shfl_xor_sync(~0u, s0, 1); s0 += __shfl_xor_sync(~0u, s0, 2);
        s1 += __shfl_xor_sync(~0u, s1, 1); s1 += __shfl_xor_sync(~0u, s1, 2);
        if (lr == 0) { reds[rl0 * 8 + colg] = s0; reds[(rl0 + 8) * 8 + colg] = s1; }
        __syncthreads();
        float lo0, hi0, lo1, hi1;
        {
            float4 ra = *(const float4*)(reds + rl0 * 8);
            float4 rb4 = *(const float4*)(reds + rl0 * 8 + 4);
            float4 rc = *(const float4*)(reds + (rl0 + 8) * 8);
            float4 rd4 = *(const float4*)(reds + (rl0 + 8) * 8 + 4);
            lo0 = ra.x + ra.y + ra.z + ra.w;   hi0 = rb4.x + rb4.y + rb4.z + rb4.w;
            lo1 = rc.x + rc.y + rc.z + rc.w;   hi1 = rd4.x + rd4.y + rd4.z + rd4.w;
        }
        const float T0 = lo0 + hi0, T1 = lo1 + hi1;
        const float inv0 = 1.f / T0, inv1 = 1.f / T1;
        const bool rlo = (tile < 8);
        if (colg == 0 && lr == 0) {
            rowsum_s[rl0]     = (rlo ? lo0 + 0.7f * hi0 : 0.7f * lo0 + hi0) * inv0 + 1.f;
            rowsum_s[rl0 + 8] = (rlo ? lo1 + 0.7f * hi1 : 0.7f * lo1 + hi1) * inv1 + 1.f;
        }
        const float msk = (rlo != (colg < 4)) ? 0.7f : 1.0f;
        if (eq0) {
#pragma unroll
            for (int t = 0; t < 8; t++)
#pragma unroll
                for (int j = 0; j < 2; j++)
                    if (((t << 1) | j) == key0) acc[t][j] = T0;
        }
        if (eq1) {
#pragma unroll
            for (int t = 0; t < 8; t++)
#pragma unroll
                for (int j = 0; j < 2; j++)
                    if (((t << 1) | j) == key1) acc[t][2 + j] = T1;
        }
        const float m0s = inv0 * msk, m1s = inv1 * msk;

#pragma unroll
        for (int tp = 0; tp < 4; tp++) {
            const int ct = colg * 64 + tp * 16;
            stsm4h(adj_s, band * 16, ct, 520,
                   h2u(acc[2*tp][0] * m0s,   acc[2*tp][1] * m0s),
                   h2u(acc[2*tp][2] * m1s,   acc[2*tp][3] * m1s),
                   h2u(acc[2*tp+1][0] * m0s, acc[2*tp+1][1] * m0s),
                   h2u(acc[2*tp+1][2] * m1s, acc[2*tp+1][3] * m1s));
        }
        __syncthreads();

        // ---- warps 0-3: y = adj @ nf (16x32 tiles); warps 4-15: adj -> global ----
        float vy[4][4];
#pragma unroll
        for (int t = 0; t < 4; t++) { vy[t][0] = vy[t][1] = vy[t][2] = vy[t][3] = 0.f; }
        const int yband = (w & 3) >> 1, ych = (w & 1) * 32;
        if (w < 4) {
#pragma unroll 4
            for (int ks = 0; ks < 32; ks += 2) {
                const int k0 = ks * 16;
                unsigned a0, a1, a2, a3; ldsm4h(a0, a1, a2, a3, adj_s, yband * 16, k0, 520);
                unsigned c0, c1, c2, c3; ldsm4h(c0, c1, c2, c3, adj_s, yband * 16, k0 + 16, 520);
#pragma unroll
                for (int nt = 0; nt < 4; nt++) {
                    unsigned b0, b1, b2v, b3v;
                    ldsm4h_t(b0, b1, b2v, b3v, nf_s, k0, ych + nt * 8, 72);
                    mma_f16(vy[nt], a0, a1, a2, a3, b0, b1);
                    mma_f16(vy[nt], c0, c1, c2, c3, b2v, b3v);
                }
            }
        } else {
            const size_t gb = ((size_t)batch * N1 + tile * 32) * N1;
            for (int e = tid - 128; e < 2048; e += 384) {
                const int r = e >> 6, c8 = e & 63;
                *(uint4*)(g_adjh + gb + (size_t)r * N1 + c8 * 8) =
                    *(const uint4*)(adj_s + r * 520 + c8 * 8);
            }
        }
        __syncthreads();   // y-phase done reading adj_s/nf_s; copy done

        // ---- stage y into adj_s head; fetch th1' into adj_s+2304 ----
        __half* y_s  = adj_s;
        __half* Wh1s = adj_s + 2304;
        if (w < 4) {
#pragma unroll
            for (int cc = 0; cc < 2; cc++) {
                stsm4h(y_s, yband * 16, ych + cc * 16, 72,
                       h2u(vy[cc*2][0], vy[cc*2][1]),   h2u(vy[cc*2][2], vy[cc*2][3]),
                       h2u(vy[cc*2+1][0], vy[cc*2+1][1]), h2u(vy[cc*2+1][2], vy[cc*2+1][3]));
            }
        }
        for (int e = tid; e < 512; e += 512)
            cp16(sptr(Wh1s + (e >> 3) * 72 + (e & 7) * 8), g_Wh + 64 * 64 + e * 8);
        CP_COMMIT; CP_WAIT0;
        __syncthreads();

        // ---- t = va + y@th1'^T + rowsum*c1 + c0 ----
        float at[4] = {0.f, 0.f, 0.f, 0.f};
        {
            unsigned zp0 = 0, zp1 = 0, zp2 = 0, zp3 = 0;
#pragma unroll
            for (int ks = 0; ks < 4; ks++) {
                const int k0 = ks * 16;
                unsigned a0, a1, a2, a3; ldsm4h(a0, a1, a2, a3, y_s, band * 16, k0, 72);
                if ((ks & 1) == 0) {
                    ldsm4h_nk(zp0, zp1, zp2, zp3, Wh1s, n0, k0, 72);
                    mma_f16(at, a0, a1, a2, a3, zp0, zp1);
                } else {
                    mma_f16(at, a0, a1, a2, a3, zp2, zp3);
                }
            }
        }
        const size_t rb = (size_t)batch * N1 + tile * 32 + rl0;
        const int cA = n0 + lr * 2;
        const float c0a = cbuf_s[cA], c0b = cbuf_s[cA + 1];
        const float c1a = cbuf_s[64 + cA], c1b = cbuf_s[64 + cA + 1];
        const float rs0 = rowsum_s[rl0], rs1 = rowsum_s[rl0 + 8];
        *(__half2*)(g_th + rb * 64 + cA) =
            __floats2half2_rn(va[0] + at[0] + rs0 * c1a + c0a,
                              va[1] + at[1] + rs0 * c1b + c0b);
        *(__half2*)(g_th + (rb + 8) * 64 + cA) =
            __floats2half2_rn(va[2] + at[2] + rs1 * c1a + c0a,
                              va[3] + at[3] + rs1 * c1b + c0b);
    }
}

// ---------------- K4: op = adj @ t + bias, 128-row tiles, 32x32 k-split ------
__global__ void __launch_bounds__(512, 2) k_out(const float* __restrict__ th0b,
                                                const float* __restrict__ th1b) {
    extern __shared__ char sraw[];
    __half* t_s = (__half*)sraw;
    __half* cbA = (__half*)(sraw + 73728);
    __half* cbB = (__half*)(sraw + 92160);
    __half* pst = cbA;                       // 8 * 32*40 halves = 20480 B
    const int tile = blockIdx.x, batch = blockIdx.y, tid = threadIdx.x;

    const __half* tg = g_th + (size_t)batch * N1 * 64;
    const __half* ag = g_adjh + ((size_t)batch * N1 + tile * 128) * N1;
    for (int e = tid; e < 4096; e += 512)
        cp16(sptr(t_s + (e >> 3) * 72 + (e & 7) * 8), tg + e * 8);
    for (int e = tid; e < 1024; e += 512) {
        const int r = e >> 3, c8 = e & 7;
        cp16(sptr(cbA + r * 72 + c8 * 8), ag + (size_t)r * N1 + c8 * 8);
    }
    CP_COMMIT;

    const int w = tid >> 5, lane = tid & 31;
    const int kh = w >> 3, sub = w & 7;
    const int rband = sub >> 1, chalf = sub & 1;
    const int lq = lane >> 2, lr = lane & 3;
    float acc[2][4][4];
#pragma unroll
    for (int rr = 0; rr < 2; rr++)
#pragma unroll
        for (int t = 0; t < 4; t++) { acc[rr][t][0] = acc[rr][t][1] = acc[rr][t][2] = acc[rr][t][3] = 0.f; }

    for (int ch = 0; ch < 8; ch++) {
        __half* cb = (ch & 1) ? cbB : cbA;
        if (ch < 7) {
            __half* nb = (ch & 1) ? cbA : cbB;
            for (int e = tid; e < 1024; e += 512) {
                const int r = e >> 3, c8 = e & 7;
                cp16(sptr(nb + r * 72 + c8 * 8), ag + (size_t)r * N1 + (ch + 1) * 64 + c8 * 8);
            }
            CP_COMMIT; CP_WAIT1;
        } else {
            CP_WAIT0;
        }
        __syncthreads();
        if ((ch >> 2) == kh) {
#pragma unroll
            for (int kp = 0; kp < 64; kp += 32) {
                unsigned a0, a1, a2, a3; ldsm4h(a0, a1, a2, a3, cb, rband * 32,      kp, 72);
                unsigned e0, e1, e2, e3; ldsm4h(e0, e1, e2, e3, cb, rband * 32,      kp + 16, 72);
                unsigned f0, f1, f2, f3; ldsm4h(f0, f1, f2, f3, cb, rband * 32 + 16, kp, 72);
                unsigned g0, g1, g2, g3; ldsm4h(g0, g1, g2, g3, cb, rband * 32 + 16, kp + 16, 72);
#pragma unroll
                for (int nt = 0; nt < 4; nt++) {
                    unsigned b0, b1, b2v, b3v;
                    ldsm4h_t(b0, b1, b2v, b3v, t_s, ch * 64 + kp, chalf * 32 + nt * 8, 72);
                    mma_f16(acc[0][nt], a0, a1, a2, a3, b0, b1);
                    mma_f16(acc[0][nt], e0, e1, e2, e3, b2v, b3v);
                    mma_f16(acc[1][nt], f0, f1, f2, f3, b0, b1);
                    mma_f16(acc[1][nt], g0, g1, g2, g3, b2v, b3v);
                }
            }
        }
        __syncthreads();
    }

    if (kh == 1) {
        __half* pt = pst + sub * 1280;
#pragma unroll
        for (int rr = 0; rr < 2; rr++)
#pragma unroll
            for (int cc = 0; cc < 2; cc++)
                stsm4h(pt, rr * 16, cc * 16, 40,
                       h2u(acc[rr][cc*2][0], acc[rr][cc*2][1]),
                       h2u(acc[rr][cc*2][2], acc[rr][cc*2][3]),
                       h2u(acc[rr][cc*2+1][0], acc[rr][cc*2+1][1]),
                       h2u(acc[rr][cc*2+1][2], acc[rr][cc*2+1][3]));
    }
    __syncthreads();
    if (kh == 0) {
        __half* pt = pst + sub * 1280;
#pragma unroll
        for (int rr = 0; rr < 2; rr++)
#pragma unroll
            for (int cc = 0; cc < 2; cc++) {
                unsigned p0, p1, p2, p3;
                ldsm4h(p0, p1, p2, p3, pt, rr * 16, cc * 16, 40);
                const __half2 h0 = *reinterpret_cast<__half2*>(&p0);
                const __half2 h1 = *reinterpret_cast<__half2*>(&p1);
                const __half2 h2 = *reinterpret_cast<__half2*>(&p2);
                const __half2 h3 = *reinterpret_cast<__half2*>(&p3);
                acc[rr][cc*2][0]   += __low2float(h0); acc[rr][cc*2][1]   += __high2float(h0);
                acc[rr][cc*2][2]   += __low2float(h1); acc[rr][cc*2][3]   += __high2float(h1);
                acc[rr][cc*2+1][0] += __low2float(h2); acc[rr][cc*2+1][1] += __high2float(h2);
                acc[rr][cc*2+1][2] += __low2float(h3); acc[rr][cc*2+1][3] += __high2float(h3);
            }
        const size_t rbase = (size_t)batch * N1 + tile * 128 + rband * 32;
#pragma unroll
        for (int rr = 0; rr < 2; rr++) {
            const size_t rb = rbase + rr * 16 + lq;
#pragma unroll
            for (int nt = 0; nt < 4; nt++) {
                const int cA = chalf * 32 + nt * 8 + lr * 2;
                const float bc0 = __ldg(th0b + cA) + __ldg(th1b + cA);
                const float bc1 = __ldg(th0b + cA + 1) + __ldg(th1b + cA + 1);
                *(__half2*)(g_oph + rb * 64 + cA) =
                    __floats2half2_rn(acc[rr][nt][0] + bc0, acc[rr][nt][1] + bc1);
                *(__half2*)(g_oph + (rb + 8) * 64 + cA) =
                    __floats2half2_rn(acc[rr][nt][2] + bc0, acc[rr][nt][3] + bc1);
            }
        }
    }
}

// ---------------- K5: BN1 affine + leaky + mean pool (half2 reads) -----------
__global__ void k_final(float* __restrict__ out) {
    const int idx = blockIdx.x * 256 + threadIdx.x;
    const int c2 = idx & 31;
    const int n = (idx >> 5) & 255;
    const int b = idx >> 13;
    const float a0 = g_coef[1][0][c2 * 2], a1 = g_coef[1][0][c2 * 2 + 1];
    const float d0 = g_coef[1][1][c2 * 2], d1 = g_coef[1][1][c2 * 2 + 1];
    float s0 = 0.f, s1 = 0.f;
#pragma unroll 2
    for (int l = 0; l < LWIN; l++)
#pragma unroll
        for (int m = 0; m < 2; m++) {
            __half2 h = *(const __half2*)(g_oph +
                (((size_t)(b * LWIN + l) * N1 + m * NNODE + n) << 6) + c2 * 2);
            float2 f = __half22float2(h);
            float v0 = a0 * f.x + d0; s0 += (v0 > 0.f) ? v0 : SLOPE * v0;
            float v1 = a1 * f.y + d1; s1 += (v1 > 0.f) ? v1 : SLOPE * v1;
        }
    *(float2*)(out + (((size_t)(b * NNODE + n)) << 6) + c2 * 2) =
        make_float2(s0 * (1.f / 32.f), s1 * (1.f / 32.f));
}

// ---------------- launch ------------------------------------------------------
extern "C" void kernel_launch(void* const* d_in, const int* in_sizes, int n_in,
                              void* d_out, int out_size) {
    const float* x    = (const float*)d_in[0];
    const float* w2   = (const float*)d_in[1];
    const float* b2   = (const float*)d_in[2];
    const float* bn0w = (const float*)d_in[3];
    const float* bn0b = (const float*)d_in[4];
    const float* th0w = (const float*)d_in[5];
    const float* th0b = (const float*)d_in[6];
    const float* th1w = (const float*)d_in[7];
    const float* th1b = (const float*)d_in[8];
    const float* bn1w = (const float*)d_in[9];
    const float* bn1b = (const float*)d_in[10];
    float* out = (float*)d_out;

    const int SMEM_ADJ = 108672;
    const int SMEM_OUT = 110592;
    cudaFuncSetAttribute(k_adj, cudaFuncAttributeMaxDynamicSharedMemorySize, SMEM_ADJ);
    cudaFuncSetAttribute(k_out, cudaFuncAttributeMaxDynamicSharedMemorySize, SMEM_OUT);

    k_nf<<<dim3(8, BP), 256>>>(x, w2, b2);
    k_stats_p1<<<BP, 256>>>(0);
    k_p2prep<<<1, 128>>>(bn0w, bn0b, th0w, th1w);
    k_adj<<<dim3(8, BP), 512, SMEM_ADJ>>>();
    k_out<<<dim3(4, BP), 512, SMEM_OUT>>>(th0b, th1b);
    k_stats_p1<<<BP, 256>>>(1);
    k_stats_p2<<<1, 64>>>(bn1w, bn1b, 1);
    k_final<<<512, 256>>>(out);
}